// round 11
// baseline (speedup 1.0000x reference)
#include <cuda_runtime.h>
#include <math.h>

// Fixed problem shape: N=100000 nodes, F_in=128, H=64, E_dim=64, E=1.6M edges.
#define NMAX 100000
#define EMAX 1600000

// Scratch (device globals — no allocation allowed)
__device__ float g_h[NMAX * 64];   // hs = (X @ W) * dinv  (pre-scaled messages)
__device__ float g_x[NMAX * 64];   // layer activations
__device__ float g_dinv[NMAX];
__device__ int   g_cnt[NMAX];      // in-degree counts
__device__ int   g_off[NMAX + 1];  // CSR row offsets
__device__ int   g_cur[NMAX];      // placement cursors
__device__ __align__(16) int g_eidx[EMAX];  // CSR column (src) indices
__device__ int   g_blksum[256];    // scan block partials
__device__ int   g_is64;           // edge_index element width flag

// packed fp32x2 FMA (sm_103a FFMA2): acc.lo += a.lo*b.lo; acc.hi += a.hi*b.hi
__device__ __forceinline__ void ffma2(unsigned long long& acc,
                                      unsigned long long a,
                                      unsigned long long b) {
    asm("fma.rn.f32x2 %0, %1, %2, %0;" : "+l"(acc) : "l"(a), "l"(b));
}
__device__ __forceinline__ float hsum2(unsigned long long p) {
    float lo, hi;
    asm("mov.b64 {%0,%1}, %2;" : "=f"(lo), "=f"(hi) : "l"(p));
    return lo + hi;
}

__device__ __forceinline__ int edge_read(const void* ei, int is64, long long idx) {
    return is64 ? (int)((const long long*)ei)[idx] : ((const int*)ei)[idx];
}

// clamp to valid node range: converts any residual dtype misread into a
// wrong-answer (caught by rel_err) instead of an async addressing trap.
__device__ __forceinline__ int clampi(int v, int n) {
    return min(max(v, 0), n - 1);
}

// ---------------------------------------- init counts + edge dtype probe
// int64 with values < 2^31 has zero high words; int32 random indices don't.
__global__ void k_init(const int* __restrict__ ei, int n) {
    int i = blockIdx.x * blockDim.x + threadIdx.x;
    if (i < n) g_cnt[i] = 0;
    if (i == 0) {
        int any = 0;
#pragma unroll
        for (int k = 1; k < 64; k += 2) any |= ei[k];
        g_is64 = (any == 0) ? 1 : 0;
    }
}

__global__ void k_count(const void* __restrict__ ei, int E, int n) {
    int e = blockIdx.x * blockDim.x + threadIdx.x;
    if (e < E) {
        int is64 = g_is64;
        int d = clampi(edge_read(ei, is64, (long long)E + e), n);  // dst row
        atomicAdd(&g_cnt[d], 1);
    }
}

// per-block (1024 elems) inclusive scan of g_cnt -> g_off[i+1]; also dinv
__global__ void k_scan1(int n) {
    __shared__ int ts[256];
    int b = blockIdx.x, tid = threadIdx.x;
    int base = b * 1024;
    int v[4];
    int sum = 0;
#pragma unroll
    for (int k = 0; k < 4; k++) {
        int i = base + tid * 4 + k;
        int c = (i < n) ? g_cnt[i] : 0;
        v[k] = c;
        sum += c;
        if (i < n) g_dinv[i] = rsqrtf((float)c + 1.0f);
    }
    ts[tid] = sum;
    __syncthreads();
    for (int o = 1; o < 256; o <<= 1) {
        int t = (tid >= o) ? ts[tid - o] : 0;
        __syncthreads();
        ts[tid] += t;
        __syncthreads();
    }
    int run = (tid > 0) ? ts[tid - 1] : 0;
#pragma unroll
    for (int k = 0; k < 4; k++) {
        int i = base + tid * 4 + k;
        run += v[k];
        if (i < n) g_off[i + 1] = run;
    }
    if (tid == 255) g_blksum[b] = ts[255];
    if (b == 0 && tid == 0) g_off[0] = 0;
}

// exclusive scan of block sums (nb <= 256), in place
__global__ void k_scan2(int nb) {
    __shared__ int s[256];
    int tid = threadIdx.x;
    s[tid] = (tid < nb) ? g_blksum[tid] : 0;
    __syncthreads();
    for (int o = 1; o < 256; o <<= 1) {
        int t = (tid >= o) ? s[tid - o] : 0;
        __syncthreads();
        s[tid] += t;
        __syncthreads();
    }
    if (tid < nb) g_blksum[tid] = (tid > 0) ? s[tid - 1] : 0;
}

// add block prefix to g_off[i+1]; also seed g_cur with the FINAL offsets
// (thread producing g_off[i+1] seeds g_cur[i+1]; thread 0 seeds g_cur[0]=0).
__global__ void k_scan3(int n) {
    int i = blockIdx.x * blockDim.x + threadIdx.x;
    if (i < n) {
        int final = g_off[i + 1] + g_blksum[i >> 10];
        g_off[i + 1] = final;
        if (i + 1 < n) g_cur[i + 1] = final;
        if (i == 0) g_cur[0] = 0;
    }
}

__global__ void k_place(const void* __restrict__ ei, int E, int n) {
    int e = blockIdx.x * blockDim.x + threadIdx.x;
    if (e < E) {
        int is64 = g_is64;
        int s = clampi(edge_read(ei, is64, e), n);                  // src row
        int d = clampi(edge_read(ei, is64, (long long)E + e), n);   // dst row
        int pos = atomicAdd(&g_cur[d], 1);
        if (pos < EMAX) g_eidx[pos] = s;
    }
}

// ------------------------------------------------- GEMM: hs = (X @ W) * dinv
// FFMA2 path: W repacked in smem so (W[k][c], W[k+1][c]) are adjacent; X rows
// give (x[k],x[k+1]) via one LDS.64. Each fma.rn.f32x2 retires 2 FMAs.
template <int K, int ROWS>
__global__ void __launch_bounds__(256, 4)
k_gemm_scale(const float* __restrict__ Xin,
             const float* __restrict__ W,
             int n, int from_gx) {
    constexpr int TPR = 256 / ROWS;   // threads per row
    constexpr int CPT = 64 / TPR;     // cols per thread
    __shared__ float Ws[K * 64];      // paired: Ws[(k>>1)*128 + c*2 + (k&1)]
    __shared__ float Xs[ROWS * K];

    const float* X = from_gx ? (const float*)g_x : Xin;
    int tid = threadIdx.x;

    // load W [K,64] (row-major) into k-paired smem layout
    for (int i = tid; i < K * 16; i += 256) {
        float4 w = ((const float4*)W)[i];
        int k  = i >> 4;
        int c0 = (i & 15) * 4;
        int base = (k >> 1) * 128 + (k & 1);
        Ws[base + (c0 + 0) * 2] = w.x;
        Ws[base + (c0 + 1) * 2] = w.y;
        Ws[base + (c0 + 2) * 2] = w.z;
        Ws[base + (c0 + 3) * 2] = w.w;
    }

    int row0 = blockIdx.x * ROWS;
    for (int i = tid; i < ROWS * (K / 4); i += 256) {
        int r = i / (K / 4);
        int kq = i % (K / 4);
        int gr = row0 + r;
        ((float4*)Xs)[i] = (gr < n)
            ? ((const float4*)X)[(size_t)gr * (K / 4) + kq]
            : make_float4(0.f, 0.f, 0.f, 0.f);
    }
    __syncthreads();

    int r = tid / TPR;
    int cq = tid % TPR;
    unsigned long long accp[CPT];
#pragma unroll
    for (int c = 0; c < CPT; c++) accp[c] = 0ull;

#pragma unroll 4
    for (int kk = 0; kk < K / 2; kk++) {
        unsigned long long xv =
            *(const unsigned long long*)(Xs + r * K + 2 * kk);  // (x[2kk],x[2kk+1])
        const ulonglong2* wr =
            (const ulonglong2*)(Ws + kk * 128 + cq * (CPT * 2));
#pragma unroll
        for (int c2 = 0; c2 < CPT / 2; c2++) {
            ulonglong2 w = wr[c2];
            ffma2(accp[2 * c2 + 0], xv, w.x);
            ffma2(accp[2 * c2 + 1], xv, w.y);
        }
    }

    int gr = row0 + r;
    if (gr < n) {
        float di = g_dinv[gr];
#pragma unroll
        for (int c = 0; c < CPT; c++)
            g_h[(size_t)gr * 64 + cq * CPT + c] = hsum2(accp[c]) * di;
    }
}

// --------------------- gather + finalize: x = relu(dinv*(Σ hs[src] + hs) + b)
// One warp per node; float2 per lane (64 cols). CSR gather, no atomics.
// Index stream consumed 4-at-a-time (int4 when aligned) so the four row
// loads issue back-to-back (MLP=4), breaking the index->row dependency chain.
__global__ void __launch_bounds__(512, 4)
k_gather(const float* __restrict__ b, int n) {
    int node = blockIdx.x * (blockDim.x >> 5) + (threadIdx.x >> 5);
    int lane = threadIdx.x & 31;
    if (node >= n) return;
    int beg = g_off[node], end = g_off[node + 1];
    const float2* __restrict__ H = (const float2*)g_h;
    float2 acc = H[(size_t)node * 32 + lane];  // self-loop term hs[node]
    float2 acc2 = make_float2(0.f, 0.f);

    int j = beg;
    // scalar head until 16B-aligned in g_eidx (base is __align__(16))
    while (j < end && (j & 3)) {
        int s = __ldg(&g_eidx[j]);
        float2 v = H[(size_t)s * 32 + lane];
        acc.x += v.x; acc.y += v.y;
        j++;
    }
    // aligned vector body: one LDG.128 of 4 indices, 4 overlapped row loads
    for (; j + 3 < end; j += 4) {
        int4 s4 = __ldg((const int4*)&g_eidx[j]);
        float2 v0 = H[(size_t)s4.x * 32 + lane];
        float2 v1 = H[(size_t)s4.y * 32 + lane];
        float2 v2 = H[(size_t)s4.z * 32 + lane];
        float2 v3 = H[(size_t)s4.w * 32 + lane];
        acc.x  += v0.x + v1.x;
        acc.y  += v0.y + v1.y;
        acc2.x += v2.x + v3.x;
        acc2.y += v2.y + v3.y;
    }
    // scalar tail
    for (; j < end; j++) {
        int s = __ldg(&g_eidx[j]);
        float2 v = H[(size_t)s * 32 + lane];
        acc.x += v.x; acc.y += v.y;
    }

    acc.x += acc2.x;
    acc.y += acc2.y;
    float di = g_dinv[node];
    float2 bb = ((const float2*)b)[lane];
    float2 r;
    r.x = fmaxf(fmaf(di, acc.x, bb.x), 0.f);
    r.y = fmaxf(fmaf(di, acc.y, bb.y), 0.f);
    ((float2*)g_x)[(size_t)node * 32 + lane] = r;
}

// ---------------------- output: out = sigmoid(g_x @ Wl + bl)^T  -> [64, n]
__global__ void __launch_bounds__(256, 4)
k_out(const float* __restrict__ Wl,
      const float* __restrict__ bl,
      float* __restrict__ out, int n) {
    __shared__ float Ws[64 * 64];   // k-paired layout
    __shared__ float xs[32 * 64];
    __shared__ float ys[64][33];
    int tid = threadIdx.x;

    for (int i = tid; i < 1024; i += 256) {
        float4 w = ((const float4*)Wl)[i];
        int k  = i >> 4;
        int c0 = (i & 15) * 4;
        int base = (k >> 1) * 128 + (k & 1);
        Ws[base + (c0 + 0) * 2] = w.x;
        Ws[base + (c0 + 1) * 2] = w.y;
        Ws[base + (c0 + 2) * 2] = w.z;
        Ws[base + (c0 + 3) * 2] = w.w;
    }

    int row0 = blockIdx.x * 32;
    for (int i = tid; i < 512; i += 256) {
        int r = i / 16, kq = i % 16;
        int gr = row0 + r;
        ((float4*)xs)[i] = (gr < n)
            ? ((const float4*)g_x)[(size_t)gr * 16 + kq]
            : make_float4(0.f, 0.f, 0.f, 0.f);
    }
    __syncthreads();

    int r = tid / 8;        // node within tile (0..31)
    int cq = tid % 8;       // col group (8 cols each)
    unsigned long long accp[8];
#pragma unroll
    for (int c = 0; c < 8; c++) accp[c] = 0ull;

#pragma unroll 4
    for (int kk = 0; kk < 32; kk++) {
        unsigned long long xv =
            *(const unsigned long long*)(xs + r * 64 + 2 * kk);
        const ulonglong2* wr = (const ulonglong2*)(Ws + kk * 128 + cq * 16);
#pragma unroll
        for (int c2 = 0; c2 < 4; c2++) {
            ulonglong2 w = wr[c2];
            ffma2(accp[2 * c2 + 0], xv, w.x);
            ffma2(accp[2 * c2 + 1], xv, w.y);
        }
    }
#pragma unroll
    for (int c = 0; c < 8; c++) {
        float a = hsum2(accp[c]) + bl[cq * 8 + c];
        float s = 1.0f / (1.0f + __expf(-a));
        ys[cq * 8 + c][r] = s;
    }
    __syncthreads();

    // coalesced transposed write: out[c * n + node]
    for (int t = tid; t < 64 * 32; t += 256) {
        int c = t >> 5, i = t & 31;
        int gi = row0 + i;
        if (gi < n) out[(size_t)c * n + gi] = ys[c][i];
    }
}

// ---------------------------------------------------------------- launch
extern "C" void kernel_launch(void* const* d_in, const int* in_sizes, int n_in,
                              void* d_out, int out_size) {
    const float* X = (const float*)d_in[0];
    const void* ei = d_in[1];
    const float* W1 = (const float*)d_in[2];
    const float* b1 = (const float*)d_in[3];
    const float* W2 = (const float*)d_in[4];
    const float* b2 = (const float*)d_in[5];
    const float* Wl = (const float*)d_in[6];
    const float* bl = (const float*)d_in[7];
    float* out = (float*)d_out;

    int n = in_sizes[0] / 128;
    int E = in_sizes[1] / 2;

    int nb  = (n + 255) / 256;
    int eb  = (E + 255) / 256;
    int nb1 = (n + 1023) / 1024;
    int gb  = (n + 15) / 16;  // gather: 16 warps/block, warp per node

    // ---- CSR build (once, both layers) + dinv; k_init also probes dtype
    k_init<<<nb, 256>>>((const int*)ei, n);
    k_count<<<eb, 256>>>(ei, E, n);
    k_scan1<<<nb1, 256>>>(n);
    k_scan2<<<1, 256>>>(nb1);
    k_scan3<<<nb, 256>>>(n);   // also seeds g_cur
    k_place<<<eb, 256>>>(ei, E, n);

    // ---- layer 1: hs = (X @ W1) * dinv ; gather+relu
    k_gemm_scale<128, 16><<<(n + 15) / 16, 256>>>(X, W1, n, 0);
    k_gather<<<gb, 512>>>(b1, n);

    // ---- layer 2: hs = (x1 @ W2) * dinv ; gather+relu
    k_gemm_scale<64, 32><<<(n + 31) / 32, 256>>>(nullptr, W2, n, 1);
    k_gather<<<gb, 512>>>(b2, n);

    // ---- output head: sigmoid(x2 @ Wl + bl)^T
    k_out<<<(n + 31) / 32, 256>>>(Wl, bl, out, n);
}

// round 16
// speedup vs baseline: 2.9489x; 2.9489x over previous
#include <cuda_runtime.h>
#include <math.h>

// Fixed problem shape: N=100000 nodes, F_in=128, H=64, E_dim=64, E=1.6M edges.
#define NMAX 100000
#define EMAX 1600000

// Scratch (device globals — no allocation allowed)
__device__ float g_h[NMAX * 64];   // hs = (X @ W) * dinv  (pre-scaled messages)
__device__ float g_x[NMAX * 64];   // layer activations
__device__ float g_dinv[NMAX];
__device__ int   g_cnt[NMAX];      // in-degree counts
__device__ int   g_off[NMAX + 1];  // CSR row offsets
__device__ int   g_cur[NMAX];      // placement cursors
__device__ __align__(16) int g_eidx[EMAX];  // CSR column (src) indices
__device__ int   g_blksum[256];    // scan block partials
__device__ int   g_is64;           // edge_index element width flag

__device__ __forceinline__ int edge_read(const void* ei, int is64, long long idx) {
    return is64 ? (int)((const long long*)ei)[idx] : ((const int*)ei)[idx];
}

__device__ __forceinline__ int clampi(int v, int n) {
    return min(max(v, 0), n - 1);
}

// ---------------------------------------- init counts + edge dtype probe
__global__ void k_init(const int* __restrict__ ei, int n) {
    int i = blockIdx.x * blockDim.x + threadIdx.x;
    if (i < n) g_cnt[i] = 0;
    if (i == 0) {
        int any = 0;
#pragma unroll
        for (int k = 1; k < 64; k += 2) any |= ei[k];
        g_is64 = (any == 0) ? 1 : 0;
    }
}

__global__ void k_count(const void* __restrict__ ei, int E, int n) {
    int e = blockIdx.x * blockDim.x + threadIdx.x;
    if (e < E) {
        int is64 = g_is64;
        int d = clampi(edge_read(ei, is64, (long long)E + e), n);  // dst row
        atomicAdd(&g_cnt[d], 1);
    }
}

// per-block (1024 elems) inclusive scan of g_cnt -> g_off[i+1]; also dinv
__global__ void k_scan1(int n) {
    __shared__ int ts[256];
    int b = blockIdx.x, tid = threadIdx.x;
    int base = b * 1024;
    int v[4];
    int sum = 0;
#pragma unroll
    for (int k = 0; k < 4; k++) {
        int i = base + tid * 4 + k;
        int c = (i < n) ? g_cnt[i] : 0;
        v[k] = c;
        sum += c;
        if (i < n) g_dinv[i] = rsqrtf((float)c + 1.0f);
    }
    ts[tid] = sum;
    __syncthreads();
    for (int o = 1; o < 256; o <<= 1) {
        int t = (tid >= o) ? ts[tid - o] : 0;
        __syncthreads();
        ts[tid] += t;
        __syncthreads();
    }
    int run = (tid > 0) ? ts[tid - 1] : 0;
#pragma unroll
    for (int k = 0; k < 4; k++) {
        int i = base + tid * 4 + k;
        run += v[k];
        if (i < n) g_off[i + 1] = run;
    }
    if (tid == 255) g_blksum[b] = ts[255];
    if (b == 0 && tid == 0) g_off[0] = 0;
}

__global__ void k_scan2(int nb) {
    __shared__ int s[256];
    int tid = threadIdx.x;
    s[tid] = (tid < nb) ? g_blksum[tid] : 0;
    __syncthreads();
    for (int o = 1; o < 256; o <<= 1) {
        int t = (tid >= o) ? s[tid - o] : 0;
        __syncthreads();
        s[tid] += t;
        __syncthreads();
    }
    if (tid < nb) g_blksum[tid] = (tid > 0) ? s[tid - 1] : 0;
}

// add block prefix; seed g_cur with final offsets
__global__ void k_scan3(int n) {
    int i = blockIdx.x * blockDim.x + threadIdx.x;
    if (i < n) {
        int final = g_off[i + 1] + g_blksum[i >> 10];
        g_off[i + 1] = final;
        if (i + 1 < n) g_cur[i + 1] = final;
        if (i == 0) g_cur[0] = 0;
    }
}

__global__ void k_place(const void* __restrict__ ei, int E, int n) {
    int e = blockIdx.x * blockDim.x + threadIdx.x;
    if (e < E) {
        int is64 = g_is64;
        int s = clampi(edge_read(ei, is64, e), n);                  // src row
        int d = clampi(edge_read(ei, is64, (long long)E + e), n);   // dst row
        int pos = atomicAdd(&g_cur[d], 1);
        if (pos < EMAX) g_eidx[pos] = s;
    }
}

// ------------------------------------------------- GEMM: hs = (X @ W) * dinv
// Register-blocked: 64-row blocks, each thread computes 4 rows x 4 cols.
// K tiled in 64-wide chunks (smem: Ws 16KB + Xs padded 17.4KB < 48KB).
// One W LDS.128 feeds 4 rows; one X scalar feeds 4 cols -> 2 B/FMA smem.
template <int K>
__global__ void __launch_bounds__(256, 4)
k_gemm_scale(const float* __restrict__ Xin,
             const float* __restrict__ W,
             int n, int from_gx) {
    constexpr int KT = 64;           // k-tile
    constexpr int XS = KT + 4;       // padded row stride (bank-conflict-free)
    __shared__ float Ws[KT * 64];
    __shared__ float Xs[64 * XS];

    const float* X = from_gx ? (const float*)g_x : Xin;
    int tid = threadIdx.x;
    int row0 = blockIdx.x * 64;
    int g  = tid >> 4;   // row group 0..15 (4 rows each)
    int cq = tid & 15;   // col group 0..15 (4 cols each)

    float acc[4][4];
#pragma unroll
    for (int i = 0; i < 4; i++)
#pragma unroll
        for (int j = 0; j < 4; j++) acc[i][j] = 0.f;

    for (int kt = 0; kt < K; kt += KT) {
        // load W rows kt..kt+KT-1 (row-major [K,64])
        for (int i = tid; i < KT * 16; i += 256)
            ((float4*)Ws)[i] = ((const float4*)(W + kt * 64))[i];
        // load X rows row0..row0+63, cols kt..kt+KT-1 (padded stride XS)
        for (int i = tid; i < 64 * 16; i += 256) {
            int r  = i >> 4;
            int kq = i & 15;
            int gr = row0 + r;
            float4 v = (gr < n)
                ? ((const float4*)X)[(size_t)gr * (K / 4) + (kt >> 2) + kq]
                : make_float4(0.f, 0.f, 0.f, 0.f);
            *(float4*)(Xs + r * XS + kq * 4) = v;
        }
        __syncthreads();

#pragma unroll 4
        for (int k = 0; k < KT; k++) {
            float4 w = *(const float4*)(Ws + k * 64 + cq * 4);
            float x0 = Xs[(g * 4 + 0) * XS + k];
            float x1 = Xs[(g * 4 + 1) * XS + k];
            float x2 = Xs[(g * 4 + 2) * XS + k];
            float x3 = Xs[(g * 4 + 3) * XS + k];
            acc[0][0] = fmaf(x0, w.x, acc[0][0]);
            acc[0][1] = fmaf(x0, w.y, acc[0][1]);
            acc[0][2] = fmaf(x0, w.z, acc[0][2]);
            acc[0][3] = fmaf(x0, w.w, acc[0][3]);
            acc[1][0] = fmaf(x1, w.x, acc[1][0]);
            acc[1][1] = fmaf(x1, w.y, acc[1][1]);
            acc[1][2] = fmaf(x1, w.z, acc[1][2]);
            acc[1][3] = fmaf(x1, w.w, acc[1][3]);
            acc[2][0] = fmaf(x2, w.x, acc[2][0]);
            acc[2][1] = fmaf(x2, w.y, acc[2][1]);
            acc[2][2] = fmaf(x2, w.z, acc[2][2]);
            acc[2][3] = fmaf(x2, w.w, acc[2][3]);
            acc[3][0] = fmaf(x3, w.x, acc[3][0]);
            acc[3][1] = fmaf(x3, w.y, acc[3][1]);
            acc[3][2] = fmaf(x3, w.z, acc[3][2]);
            acc[3][3] = fmaf(x3, w.w, acc[3][3]);
        }
        __syncthreads();
    }

#pragma unroll
    for (int i = 0; i < 4; i++) {
        int gr = row0 + g * 4 + i;
        if (gr < n) {
            float di = g_dinv[gr];
            float4 o;
            o.x = acc[i][0] * di;
            o.y = acc[i][1] * di;
            o.z = acc[i][2] * di;
            o.w = acc[i][3] * di;
            *(float4*)(g_h + (size_t)gr * 64 + cq * 4) = o;
        }
    }
}

// --------------------- gather + finalize: x = relu(dinv*(Σ hs[src] + hs) + b)
// One warp per node; float2 per lane. 8 row loads in flight (MLP=8).
__global__ void __launch_bounds__(512, 4)
k_gather(const float* __restrict__ b, int n) {
    int node = blockIdx.x * (blockDim.x >> 5) + (threadIdx.x >> 5);
    int lane = threadIdx.x & 31;
    if (node >= n) return;
    int beg = g_off[node], end = g_off[node + 1];
    const float2* __restrict__ H = (const float2*)g_h;
    float2 acc = H[(size_t)node * 32 + lane];  // self-loop term hs[node]
    float2 acc2 = make_float2(0.f, 0.f);
    float2 acc3 = make_float2(0.f, 0.f);
    float2 acc4 = make_float2(0.f, 0.f);

    int j = beg;
    while (j < end && (j & 3)) {
        int s = __ldg(&g_eidx[j]);
        float2 v = H[(size_t)s * 32 + lane];
        acc.x += v.x; acc.y += v.y;
        j++;
    }
    for (; j + 7 < end; j += 8) {
        int4 sa = __ldg((const int4*)&g_eidx[j]);
        int4 sb = __ldg((const int4*)&g_eidx[j + 4]);
        float2 v0 = H[(size_t)sa.x * 32 + lane];
        float2 v1 = H[(size_t)sa.y * 32 + lane];
        float2 v2 = H[(size_t)sa.z * 32 + lane];
        float2 v3 = H[(size_t)sa.w * 32 + lane];
        float2 v4 = H[(size_t)sb.x * 32 + lane];
        float2 v5 = H[(size_t)sb.y * 32 + lane];
        float2 v6 = H[(size_t)sb.z * 32 + lane];
        float2 v7 = H[(size_t)sb.w * 32 + lane];
        acc.x  += v0.x + v1.x;  acc.y  += v0.y + v1.y;
        acc2.x += v2.x + v3.x;  acc2.y += v2.y + v3.y;
        acc3.x += v4.x + v5.x;  acc3.y += v4.y + v5.y;
        acc4.x += v6.x + v7.x;  acc4.y += v6.y + v7.y;
    }
    if (j + 3 < end) {
        int4 s4 = __ldg((const int4*)&g_eidx[j]);
        float2 v0 = H[(size_t)s4.x * 32 + lane];
        float2 v1 = H[(size_t)s4.y * 32 + lane];
        float2 v2 = H[(size_t)s4.z * 32 + lane];
        float2 v3 = H[(size_t)s4.w * 32 + lane];
        acc.x  += v0.x + v1.x;  acc.y  += v0.y + v1.y;
        acc2.x += v2.x + v3.x;  acc2.y += v2.y + v3.y;
        j += 4;
    }
    for (; j < end; j++) {
        int s = __ldg(&g_eidx[j]);
        float2 v = H[(size_t)s * 32 + lane];
        acc.x += v.x; acc.y += v.y;
    }

    acc.x += acc2.x + acc3.x + acc4.x;
    acc.y += acc2.y + acc3.y + acc4.y;
    float di = g_dinv[node];
    float2 bb = ((const float2*)b)[lane];
    float2 r;
    r.x = fmaxf(fmaf(di, acc.x, bb.x), 0.f);
    r.y = fmaxf(fmaf(di, acc.y, bb.y), 0.f);
    ((float2*)g_x)[(size_t)node * 32 + lane] = r;
}

// ---------------------- output: out = sigmoid(g_x @ Wl + bl)^T  -> [64, n]
// Register-blocked 2 rows x 4 cols per thread.
__global__ void __launch_bounds__(256, 4)
k_out(const float* __restrict__ Wl,
      const float* __restrict__ bl,
      float* __restrict__ out, int n) {
    constexpr int XS = 68;           // padded row stride
    __shared__ float Ws[64 * 64];    // 16KB
    __shared__ float xs[32 * XS];    // 8.5KB
    __shared__ float ys[64][33];     // 8.4KB
    int tid = threadIdx.x;

    for (int i = tid; i < 1024; i += 256)
        ((float4*)Ws)[i] = ((const float4*)Wl)[i];

    int row0 = blockIdx.x * 32;
    for (int i = tid; i < 512; i += 256) {
        int r = i >> 4, kq = i & 15;
        int gr = row0 + r;
        float4 v = (gr < n)
            ? ((const float4*)g_x)[(size_t)gr * 16 + kq]
            : make_float4(0.f, 0.f, 0.f, 0.f);
        *(float4*)(xs + r * XS + kq * 4) = v;
    }
    __syncthreads();

    int g  = tid >> 4;   // row group 0..15 (2 rows)
    int cq = tid & 15;   // col group 0..15 (4 cols)
    float acc[2][4];
#pragma unroll
    for (int i = 0; i < 2; i++)
#pragma unroll
        for (int j = 0; j < 4; j++) acc[i][j] = 0.f;

#pragma unroll 4
    for (int k = 0; k < 64; k++) {
        float4 w = *(const float4*)(Ws + k * 64 + cq * 4);
        float x0 = xs[(g * 2 + 0) * XS + k];
        float x1 = xs[(g * 2 + 1) * XS + k];
        acc[0][0] = fmaf(x0, w.x, acc[0][0]);
        acc[0][1] = fmaf(x0, w.y, acc[0][1]);
        acc[0][2] = fmaf(x0, w.z, acc[0][2]);
        acc[0][3] = fmaf(x0, w.w, acc[0][3]);
        acc[1][0] = fmaf(x1, w.x, acc[1][0]);
        acc[1][1] = fmaf(x1, w.y, acc[1][1]);
        acc[1][2] = fmaf(x1, w.z, acc[1][2]);
        acc[1][3] = fmaf(x1, w.w, acc[1][3]);
    }
#pragma unroll
    for (int i = 0; i < 2; i++) {
        int r = g * 2 + i;
#pragma unroll
        for (int j = 0; j < 4; j++) {
            float a = acc[i][j] + bl[cq * 4 + j];
            ys[cq * 4 + j][r] = 1.0f / (1.0f + __expf(-a));
        }
    }
    __syncthreads();

    // coalesced transposed write: out[c * n + node]
    for (int t = tid; t < 64 * 32; t += 256) {
        int c = t >> 5, i = t & 31;
        int gi = row0 + i;
        if (gi < n) out[(size_t)c * n + gi] = ys[c][i];
    }
}

// ---------------------------------------------------------------- launch
extern "C" void kernel_launch(void* const* d_in, const int* in_sizes, int n_in,
                              void* d_out, int out_size) {
    const float* X = (const float*)d_in[0];
    const void* ei = d_in[1];
    const float* W1 = (const float*)d_in[2];
    const float* b1 = (const float*)d_in[3];
    const float* W2 = (const float*)d_in[4];
    const float* b2 = (const float*)d_in[5];
    const float* Wl = (const float*)d_in[6];
    const float* bl = (const float*)d_in[7];
    float* out = (float*)d_out;

    int n = in_sizes[0] / 128;
    int E = in_sizes[1] / 2;

    int nb  = (n + 255) / 256;
    int eb  = (E + 255) / 256;
    int nb1 = (n + 1023) / 1024;
    int gb  = (n + 15) / 16;    // gather: 16 warps/block, warp per node
    int mb  = (n + 63) / 64;    // gemm: 64-row blocks

    // ---- CSR build (once, both layers) + dinv; k_init also probes dtype
    k_init<<<nb, 256>>>((const int*)ei, n);
    k_count<<<eb, 256>>>(ei, E, n);
    k_scan1<<<nb1, 256>>>(n);
    k_scan2<<<1, 256>>>(nb1);
    k_scan3<<<nb, 256>>>(n);   // also seeds g_cur
    k_place<<<eb, 256>>>(ei, E, n);

    // ---- layer 1: hs = (X @ W1) * dinv ; gather+relu
    k_gemm_scale<128><<<mb, 256>>>(X, W1, n, 0);
    k_gather<<<gb, 512>>>(b1, n);

    // ---- layer 2: hs = (x1 @ W2) * dinv ; gather+relu
    k_gemm_scale<64><<<mb, 256>>>(nullptr, W2, n, 1);
    k_gather<<<gb, 512>>>(b2, n);

    // ---- output head: sigmoid(x2 @ Wl + bl)^T
    k_out<<<(n + 31) / 32, 256>>>(Wl, bl, out, n);
}